// round 4
// baseline (speedup 1.0000x reference)
#include <cuda_runtime.h>
#include <cstdint>

#define N_NODES 50000
#define E_EDGES 800000
#define HDIM    96
#define CIN     128

// ---------------- device scratch (no allocations allowed) ----------------
__device__ int   g_edeg[N_NODES];
__device__ int   g_rowstart[N_NODES + 1];
__device__ int   g_pos[N_NODES];
__device__ float g_dinv[N_NODES];
__device__ int   g_csr[E_EDGES];
__device__ float g_hs[(size_t)N_NODES * HDIM];   // (X@W) * dinv[row]
__device__ float g_act[(size_t)N_NODES * HDIM];  // layer-1 activations

// ---------------- CSR build ----------------
__global__ void k_zero_deg() {
    int i = blockIdx.x * blockDim.x + threadIdx.x;
    if (i < N_NODES) g_edeg[i] = 0;
}

__global__ void k_count(const int* __restrict__ ei) {
    int e = blockIdx.x * blockDim.x + threadIdx.x;
    if (e < E_EDGES) atomicAdd(&g_edeg[ei[E_EDGES + e]], 1);
}

// single-block exclusive scan over g_edeg -> rowstart/pos, plus dinv = rsqrt(deg+1)
__global__ void k_scan() {
    __shared__ int warp_off[32];
    __shared__ int s_carry;
    int tid = threadIdx.x, lane = tid & 31, wid = tid >> 5;
    if (tid == 0) s_carry = 0;
    __syncthreads();
    for (int base = 0; base < N_NODES; base += 1024) {
        int i = base + tid;
        int v = (i < N_NODES) ? g_edeg[i] : 0;
        int incl = v;
        #pragma unroll
        for (int off = 1; off < 32; off <<= 1) {
            int t = __shfl_up_sync(0xffffffffu, incl, off);
            if (lane >= off) incl += t;
        }
        if (lane == 31) warp_off[wid] = incl;
        __syncthreads();
        if (wid == 0) {
            int ws = warp_off[lane];
            int wincl = ws;
            #pragma unroll
            for (int off = 1; off < 32; off <<= 1) {
                int t = __shfl_up_sync(0xffffffffu, wincl, off);
                if (lane >= off) wincl += t;
            }
            warp_off[lane] = wincl - ws;  // exclusive offsets of warps
        }
        __syncthreads();
        int excl = (incl - v) + warp_off[wid] + s_carry;
        if (i < N_NODES) {
            g_rowstart[i] = excl;
            g_pos[i] = excl;
            g_dinv[i] = rsqrtf((float)(v + 1));  // deg includes self-loop
        }
        __syncthreads();
        if (tid == 1023) s_carry = excl + v;
        __syncthreads();
    }
    if (tid == 0) g_rowstart[N_NODES] = s_carry;
}

__global__ void k_fill(const int* __restrict__ ei) {
    int e = blockIdx.x * blockDim.x + threadIdx.x;
    if (e < E_EDGES) {
        int dst = ei[E_EDGES + e];
        int src = ei[e];
        int slot = atomicAdd(&g_pos[dst], 1);
        g_csr[slot] = src;
    }
}

// ---------------- GEMM: g_hs = (X @ W) * dinv[row] ----------------
// X = X_ext if non-null, else g_act (device-side resolution of scratch).
// Tile: 128 rows x 96 cols per block, 256 threads, each thread 8x6 outputs.
// K chunked by 32: Xs 128x36 (pad 4) + Ws 32x96 = 30.75 KB static smem.
template <int KDIM>
__global__ void __launch_bounds__(256) k_gemm(const float* __restrict__ X_ext,
                                              const float* __restrict__ W) {
    const float* X = X_ext ? X_ext : (const float*)g_act;
    __shared__ float Xs[128 * 36];
    __shared__ float Ws[32 * 96];
    int tid = threadIdx.x;
    int txc = tid & 15;        // col group: cols = txc + 16*j, j=0..5
    int tyr = tid >> 4;        // row group: rows = tyr*8 + i, i=0..7
    int rbase = blockIdx.x * 128;

    float acc[8][6];
    #pragma unroll
    for (int i = 0; i < 8; i++)
        #pragma unroll
        for (int j = 0; j < 6; j++) acc[i][j] = 0.0f;

    for (int k0 = 0; k0 < KDIM; k0 += 32) {
        __syncthreads();
        // load X chunk: 128 rows x 32 floats = 1024 float4
        #pragma unroll
        for (int t = tid; t < 1024; t += 256) {
            int row = t >> 3;
            int kk = (t & 7) << 2;
            int gr = rbase + row;
            float4 v = make_float4(0.f, 0.f, 0.f, 0.f);
            if (gr < N_NODES)
                v = *reinterpret_cast<const float4*>(X + (size_t)gr * KDIM + k0 + kk);
            *reinterpret_cast<float4*>(&Xs[row * 36 + kk]) = v;
        }
        // load W chunk: 32 x 96 = 768 float4
        #pragma unroll
        for (int t = tid; t < 768; t += 256) {
            int kk = t / 24;
            int cc = (t % 24) << 2;
            *reinterpret_cast<float4*>(&Ws[kk * 96 + cc]) =
                *reinterpret_cast<const float4*>(W + (size_t)(k0 + kk) * HDIM + cc);
        }
        __syncthreads();
        #pragma unroll 8
        for (int kk = 0; kk < 32; kk++) {
            float xv[8], wv[6];
            #pragma unroll
            for (int i = 0; i < 8; i++) xv[i] = Xs[(tyr * 8 + i) * 36 + kk];
            #pragma unroll
            for (int j = 0; j < 6; j++) wv[j] = Ws[kk * 96 + txc + 16 * j];
            #pragma unroll
            for (int i = 0; i < 8; i++)
                #pragma unroll
                for (int j = 0; j < 6; j++) acc[i][j] = fmaf(xv[i], wv[j], acc[i][j]);
        }
    }

    #pragma unroll
    for (int i = 0; i < 8; i++) {
        int gr = rbase + tyr * 8 + i;
        if (gr < N_NODES) {
            float dv = g_dinv[gr];
            #pragma unroll
            for (int j = 0; j < 6; j++)
                g_hs[(size_t)gr * HDIM + txc + 16 * j] = acc[i][j] * dv;
        }
    }
}

// ---------------- aggregate + bias + layernorm + prelu, warp per node ----------------
// Reads g_hs; writes out_ext if non-null, else g_act.
// float4 gather: 24 active lanes x LDG.128 per row (96 floats = 24 float4).
// Dual accumulator chains for memory-level parallelism.
__global__ void __launch_bounds__(256) k_agg(const float* __restrict__ bias,
                                             const float* __restrict__ gam,
                                             const float* __restrict__ bet,
                                             const float* __restrict__ pa,
                                             float* __restrict__ out_ext) {
    const float4* hs4 = (const float4*)g_hs;   // 24 float4 per row
    float* outp = out_ext ? out_ext : (float*)g_act;

    int warp = (blockIdx.x * blockDim.x + threadIdx.x) >> 5;
    int lane = threadIdx.x & 31;
    if (warp >= N_NODES) return;
    int node = warp;
    int start = g_rowstart[node];
    int end = g_rowstart[node + 1];
    bool act = lane < 24;

    float4 A = make_float4(0.f, 0.f, 0.f, 0.f);
    float4 C = make_float4(0.f, 0.f, 0.f, 0.f);
    for (int e0 = start; e0 < end; e0 += 32) {
        int cnt = min(32, end - e0);
        int s = (lane < cnt) ? g_csr[e0 + lane] : 0;
        int j = 0;
        for (; j + 2 <= cnt; j += 2) {
            int sj0 = __shfl_sync(0xffffffffu, s, j);
            int sj1 = __shfl_sync(0xffffffffu, s, j + 1);
            if (act) {
                float4 v0 = __ldg(&hs4[(size_t)sj0 * 24 + lane]);
                float4 v1 = __ldg(&hs4[(size_t)sj1 * 24 + lane]);
                A.x += v0.x; A.y += v0.y; A.z += v0.z; A.w += v0.w;
                C.x += v1.x; C.y += v1.y; C.z += v1.z; C.w += v1.w;
            }
        }
        if (j < cnt) {
            int sj = __shfl_sync(0xffffffffu, s, j);
            if (act) {
                float4 v = __ldg(&hs4[(size_t)sj * 24 + lane]);
                A.x += v.x; A.y += v.y; A.z += v.z; A.w += v.w;
            }
        }
    }
    float dv = g_dinv[node];
    float4 bb = make_float4(0.f, 0.f, 0.f, 0.f);
    float4 gg = bb, ee = bb, aa = bb;
    if (act) {
        // self-loop: hs[i] * dinv[i] (dv applied below)
        float4 vs = __ldg(&hs4[(size_t)node * 24 + lane]);
        A.x += C.x + vs.x; A.y += C.y + vs.y; A.z += C.z + vs.z; A.w += C.w + vs.w;
        bb = *(const float4*)(bias + lane * 4);
        gg = *(const float4*)(gam  + lane * 4);
        ee = *(const float4*)(bet  + lane * 4);
        aa = *(const float4*)(pa   + lane * 4);
    }

    float t0 = A.x * dv + bb.x;
    float t1 = A.y * dv + bb.y;
    float t2 = A.z * dv + bb.z;
    float t3 = A.w * dv + bb.w;
    if (!act) { t0 = t1 = t2 = t3 = 0.f; }

    // layernorm over 96 channels (4 per active lane, inactive lanes contribute 0)
    float s = t0 + t1 + t2 + t3;
    #pragma unroll
    for (int off = 16; off; off >>= 1) s += __shfl_xor_sync(0xffffffffu, s, off);
    float mu = s * (1.0f / 96.0f);
    float d0 = t0 - mu, d1 = t1 - mu, d2 = t2 - mu, d3 = t3 - mu;
    float q = act ? (d0 * d0 + d1 * d1 + d2 * d2 + d3 * d3) : 0.f;
    #pragma unroll
    for (int off = 16; off; off >>= 1) q += __shfl_xor_sync(0xffffffffu, q, off);
    float rstd = rsqrtf(q * (1.0f / 96.0f) + 1e-5f);

    if (act) {
        float y0 = d0 * rstd * gg.x + ee.x;
        float y1 = d1 * rstd * gg.y + ee.y;
        float y2 = d2 * rstd * gg.z + ee.z;
        float y3 = d3 * rstd * gg.w + ee.w;
        if (y0 < 0.f) y0 *= aa.x;
        if (y1 < 0.f) y1 *= aa.y;
        if (y2 < 0.f) y2 *= aa.z;
        if (y3 < 0.f) y3 *= aa.w;
        ((float4*)(outp + (size_t)node * HDIM))[lane] = make_float4(y0, y1, y2, y3);
    }
}

extern "C" void kernel_launch(void* const* d_in, const int* in_sizes, int n_in,
                              void* d_out, int out_size) {
    const float* x   = (const float*)d_in[0];
    const int*   ei  = (const int*)d_in[1];
    const float* W1  = (const float*)d_in[2];
    const float* b1  = (const float*)d_in[3];
    const float* W2  = (const float*)d_in[4];
    const float* b2  = (const float*)d_in[5];
    const float* g1  = (const float*)d_in[6];
    const float* be1 = (const float*)d_in[7];
    const float* g2  = (const float*)d_in[8];
    const float* be2 = (const float*)d_in[9];
    const float* pa  = (const float*)d_in[10];
    float* out = (float*)d_out;

    const int TB = 256;
    // CSR build (recomputed every launch; edges are an input)
    k_zero_deg<<<(N_NODES + TB - 1) / TB, TB>>>();
    k_count<<<(E_EDGES + TB - 1) / TB, TB>>>(ei);
    k_scan<<<1, 1024>>>();
    k_fill<<<(E_EDGES + TB - 1) / TB, TB>>>(ei);

    int gemm_blocks = (N_NODES + 127) / 128;
    int agg_blocks = (N_NODES + 7) / 8;  // 8 warps/block, warp per node

    // layer 1: gemm(x,W1) -> g_hs ; agg -> g_act
    k_gemm<CIN><<<gemm_blocks, 256>>>(x, W1);
    k_agg<<<agg_blocks, 256>>>(b1, g1, be1, pa, nullptr);
    // layer 2: gemm(g_act,W2) -> g_hs ; agg -> out
    k_gemm<HDIM><<<gemm_blocks, 256>>>(nullptr, W2);
    k_agg<<<agg_blocks, 256>>>(b2, g2, be2, pa, out);
}

// round 8
// speedup vs baseline: 1.1578x; 1.1578x over previous
#include <cuda_runtime.h>
#include <cstdint>

#define N_NODES 50000
#define E_EDGES 800000
#define HDIM    96
#define CIN     128

#define SCAN_BLK 512
#define SCAN_NBLK ((N_NODES + SCAN_BLK - 1) / SCAN_BLK)   // 98

// ---------------- device scratch (no allocations allowed) ----------------
__device__ int   g_edeg[N_NODES];
__device__ int   g_rowstart[N_NODES + 1];
__device__ int   g_pos[N_NODES];
__device__ float g_dinv[N_NODES];
__device__ int   g_csr[E_EDGES];
__device__ int   g_part[SCAN_NBLK];     // per-block sums
__device__ int   g_part2[SCAN_NBLK];    // exclusive-scanned block offsets
__device__ float g_hs[(size_t)N_NODES * HDIM];   // (X@W) * dinv[row]
__device__ float g_act[(size_t)N_NODES * HDIM];  // layer-1 activations

// ---------------- CSR build ----------------
__global__ void k_zero_deg() {
    int i = blockIdx.x * blockDim.x + threadIdx.x;
    if (i < N_NODES) g_edeg[i] = 0;
}

__global__ void k_count(const int* __restrict__ ei) {
    int e = blockIdx.x * blockDim.x + threadIdx.x;
    if (e < E_EDGES) atomicAdd(&g_edeg[ei[E_EDGES + e]], 1);
}

// step 1: per-block sums of g_edeg
__global__ void __launch_bounds__(SCAN_BLK) k_bsum() {
    __shared__ int wsum[SCAN_BLK / 32];
    int i = blockIdx.x * SCAN_BLK + threadIdx.x;
    int lane = threadIdx.x & 31, wid = threadIdx.x >> 5;
    int v = (i < N_NODES) ? g_edeg[i] : 0;
    int s = v;
    #pragma unroll
    for (int off = 16; off; off >>= 1) s += __shfl_xor_sync(0xffffffffu, s, off);
    if (lane == 0) wsum[wid] = s;
    __syncthreads();
    if (wid == 0) {
        int t = (lane < SCAN_BLK / 32) ? wsum[lane] : 0;
        #pragma unroll
        for (int off = 16; off; off >>= 1) t += __shfl_xor_sync(0xffffffffu, t, off);
        if (lane == 0) g_part[blockIdx.x] = t;
    }
}

// step 2: exclusive scan of the SCAN_NBLK partials (single 128-thread block)
__global__ void k_scanpart() {
    __shared__ int woff[4];
    int t = threadIdx.x, lane = t & 31, wid = t >> 5;
    int v = (t < SCAN_NBLK) ? g_part[t] : 0;
    int incl = v;
    #pragma unroll
    for (int off = 1; off < 32; off <<= 1) {
        int u = __shfl_up_sync(0xffffffffu, incl, off);
        if (lane >= off) incl += u;
    }
    if (lane == 31) woff[wid] = incl;
    __syncthreads();
    int wo = 0;
    #pragma unroll
    for (int w = 0; w < 4; w++) if (w < wid) wo += woff[w];
    if (t < SCAN_NBLK) g_part2[t] = incl - v + wo;
    if (t == 127) g_rowstart[N_NODES] = wo + incl;  // total (= E_EDGES)
}

// step 3: local exclusive scan + block offset -> rowstart/pos/dinv
__global__ void __launch_bounds__(SCAN_BLK) k_apply() {
    __shared__ int warp_off[SCAN_BLK / 32];
    int i = blockIdx.x * SCAN_BLK + threadIdx.x;
    int lane = threadIdx.x & 31, wid = threadIdx.x >> 5;
    int v = (i < N_NODES) ? g_edeg[i] : 0;
    int incl = v;
    #pragma unroll
    for (int off = 1; off < 32; off <<= 1) {
        int u = __shfl_up_sync(0xffffffffu, incl, off);
        if (lane >= off) incl += u;
    }
    if (lane == 31) warp_off[wid] = incl;
    __syncthreads();
    if (wid == 0) {
        int ws = (lane < SCAN_BLK / 32) ? warp_off[lane] : 0;
        int wincl = ws;
        #pragma unroll
        for (int off = 1; off < 32; off <<= 1) {
            int u = __shfl_up_sync(0xffffffffu, wincl, off);
            if (lane >= off) wincl += u;
        }
        if (lane < SCAN_BLK / 32) warp_off[lane] = wincl - ws;
    }
    __syncthreads();
    if (i < N_NODES) {
        int excl = (incl - v) + warp_off[wid] + g_part2[blockIdx.x];
        g_rowstart[i] = excl;
        g_pos[i] = excl;
        g_dinv[i] = rsqrtf((float)(v + 1));   // deg includes self-loop
    }
}

__global__ void k_fill(const int* __restrict__ ei) {
    int e = blockIdx.x * blockDim.x + threadIdx.x;
    if (e < E_EDGES) {
        int dst = ei[E_EDGES + e];
        int src = ei[e];
        int slot = atomicAdd(&g_pos[dst], 1);
        g_csr[slot] = src;
    }
}

// ---------------- GEMM: g_hs = (X @ W) * dinv[row], packed f32x2 ----------------
// X = X_ext if non-null, else g_act. Tile 128 rows x 96 cols, 256 threads.
// Each thread: 8 rows x 3 adjacent col-PAIRS, accumulated in fma.rn.f32x2.
// Xs2: X duplicated (v,v) per k as u64, row-padded to 33 (bank-clean LDS.64).
// Ws: plain float 32x96; col-pairs read directly as LDS.64.
// Static smem: 128*33*8 + 32*96*4 = 46080 B.
template <int KDIM>
__global__ void __launch_bounds__(256) k_gemm(const float* __restrict__ X_ext,
                                              const float* __restrict__ W) {
    const float* X = X_ext ? X_ext : (const float*)g_act;
    __shared__ unsigned long long Xs2[128 * 33];
    __shared__ float Ws[32 * 96];
    int tid = threadIdx.x;
    int txc = tid & 15;        // col-pair group: pairs at c = txc*2 + 32*j, j=0..2
    int tyr = tid >> 4;        // row group: rows = tyr*8 + i, i=0..7
    int rbase = blockIdx.x * 128;

    unsigned long long acc[8][3];
    #pragma unroll
    for (int i = 0; i < 8; i++)
        #pragma unroll
        for (int j = 0; j < 3; j++) acc[i][j] = 0ull;  // (0.0f, 0.0f)

    for (int k0 = 0; k0 < KDIM; k0 += 32) {
        __syncthreads();
        // load X chunk: 128 rows x 32 floats; store duplicated (v,v) as float2
        #pragma unroll
        for (int t = tid; t < 1024; t += 256) {
            int row = t >> 3;
            int kk4 = (t & 7) << 2;
            int gr = rbase + row;
            float4 v = make_float4(0.f, 0.f, 0.f, 0.f);
            if (gr < N_NODES)
                v = *reinterpret_cast<const float4*>(X + (size_t)gr * KDIM + k0 + kk4);
            int base = row * 33 + kk4;
            ((float2*)&Xs2[base + 0])[0] = make_float2(v.x, v.x);
            ((float2*)&Xs2[base + 1])[0] = make_float2(v.y, v.y);
            ((float2*)&Xs2[base + 2])[0] = make_float2(v.z, v.z);
            ((float2*)&Xs2[base + 3])[0] = make_float2(v.w, v.w);
        }
        // load W chunk: 32 x 96 = 768 float4
        #pragma unroll
        for (int t = tid; t < 768; t += 256) {
            int kk = t / 24;
            int cc = (t % 24) << 2;
            *reinterpret_cast<float4*>(&Ws[kk * 96 + cc]) =
                *reinterpret_cast<const float4*>(W + (size_t)(k0 + kk) * HDIM + cc);
        }
        __syncthreads();
        #pragma unroll 4
        for (int kk = 0; kk < 32; kk++) {
            unsigned long long xv[8], wv[3];
            #pragma unroll
            for (int i = 0; i < 8; i++)
                xv[i] = Xs2[(tyr * 8 + i) * 33 + kk];
            #pragma unroll
            for (int j = 0; j < 3; j++)
                wv[j] = *reinterpret_cast<const unsigned long long*>(
                            &Ws[kk * 96 + txc * 2 + 32 * j]);
            #pragma unroll
            for (int i = 0; i < 8; i++)
                #pragma unroll
                for (int j = 0; j < 3; j++)
                    asm("fma.rn.f32x2 %0, %1, %2, %0;"
                        : "+l"(acc[i][j]) : "l"(xv[i]), "l"(wv[j]));
        }
    }

    #pragma unroll
    for (int i = 0; i < 8; i++) {
        int gr = rbase + tyr * 8 + i;
        if (gr < N_NODES) {
            float dv = g_dinv[gr];
            #pragma unroll
            for (int j = 0; j < 3; j++) {
                float2 p = *reinterpret_cast<float2*>(&acc[i][j]);
                p.x *= dv; p.y *= dv;
                *reinterpret_cast<float2*>(
                    g_hs + (size_t)gr * HDIM + txc * 2 + 32 * j) = p;
            }
        }
    }
}

// ---------------- aggregate + bias + layernorm + prelu, warp per node ----------------
// Reads g_hs; writes out_ext if non-null, else g_act.
// float4 gather: 24 active lanes x LDG.128 per row (96 floats = 24 float4).
// Dual accumulator chains for memory-level parallelism.
__global__ void __launch_bounds__(256) k_agg(const float* __restrict__ bias,
                                             const float* __restrict__ gam,
                                             const float* __restrict__ bet,
                                             const float* __restrict__ pa,
                                             float* __restrict__ out_ext) {
    const float4* hs4 = (const float4*)g_hs;   // 24 float4 per row
    float* outp = out_ext ? out_ext : (float*)g_act;

    int warp = (blockIdx.x * blockDim.x + threadIdx.x) >> 5;
    int lane = threadIdx.x & 31;
    if (warp >= N_NODES) return;
    int node = warp;
    int start = g_rowstart[node];
    int end = g_rowstart[node + 1];
    bool act = lane < 24;

    float4 A = make_float4(0.f, 0.f, 0.f, 0.f);
    float4 C = make_float4(0.f, 0.f, 0.f, 0.f);
    for (int e0 = start; e0 < end; e0 += 32) {
        int cnt = min(32, end - e0);
        int s = (lane < cnt) ? g_csr[e0 + lane] : 0;
        int j = 0;
        for (; j + 2 <= cnt; j += 2) {
            int sj0 = __shfl_sync(0xffffffffu, s, j);
            int sj1 = __shfl_sync(0xffffffffu, s, j + 1);
            if (act) {
                float4 v0 = __ldg(&hs4[(size_t)sj0 * 24 + lane]);
                float4 v1 = __ldg(&hs4[(size_t)sj1 * 24 + lane]);
                A.x += v0.x; A.y += v0.y; A.z += v0.z; A.w += v0.w;
                C.x += v1.x; C.y += v1.y; C.z += v1.z; C.w += v1.w;
            }
        }
        if (j < cnt) {
            int sj = __shfl_sync(0xffffffffu, s, j);
            if (act) {
                float4 v = __ldg(&hs4[(size_t)sj * 24 + lane]);
                A.x += v.x; A.y += v.y; A.z += v.z; A.w += v.w;
            }
        }
    }
    float dv = g_dinv[node];
    float4 bb = make_float4(0.f, 0.f, 0.f, 0.f);
    float4 gg = bb, ee = bb, aa = bb;
    if (act) {
        // self-loop: hs[i] * dinv[i] (dv applied below)
        float4 vs = __ldg(&hs4[(size_t)node * 24 + lane]);
        A.x += C.x + vs.x; A.y += C.y + vs.y; A.z += C.z + vs.z; A.w += C.w + vs.w;
        bb = *(const float4*)(bias + lane * 4);
        gg = *(const float4*)(gam  + lane * 4);
        ee = *(const float4*)(bet  + lane * 4);
        aa = *(const float4*)(pa   + lane * 4);
    }

    float t0 = A.x * dv + bb.x;
    float t1 = A.y * dv + bb.y;
    float t2 = A.z * dv + bb.z;
    float t3 = A.w * dv + bb.w;
    if (!act) { t0 = t1 = t2 = t3 = 0.f; }

    // layernorm over 96 channels (4 per active lane, inactive lanes contribute 0)
    float s = t0 + t1 + t2 + t3;
    #pragma unroll
    for (int off = 16; off; off >>= 1) s += __shfl_xor_sync(0xffffffffu, s, off);
    float mu = s * (1.0f / 96.0f);
    float d0 = t0 - mu, d1 = t1 - mu, d2 = t2 - mu, d3 = t3 - mu;
    float q = act ? (d0 * d0 + d1 * d1 + d2 * d2 + d3 * d3) : 0.f;
    #pragma unroll
    for (int off = 16; off; off >>= 1) q += __shfl_xor_sync(0xffffffffu, q, off);
    float rstd = rsqrtf(q * (1.0f / 96.0f) + 1e-5f);

    if (act) {
        float y0 = d0 * rstd * gg.x + ee.x;
        float y1 = d1 * rstd * gg.y + ee.y;
        float y2 = d2 * rstd * gg.z + ee.z;
        float y3 = d3 * rstd * gg.w + ee.w;
        if (y0 < 0.f) y0 *= aa.x;
        if (y1 < 0.f) y1 *= aa.y;
        if (y2 < 0.f) y2 *= aa.z;
        if (y3 < 0.f) y3 *= aa.w;
        ((float4*)(outp + (size_t)node * HDIM))[lane] = make_float4(y0, y1, y2, y3);
    }
}

extern "C" void kernel_launch(void* const* d_in, const int* in_sizes, int n_in,
                              void* d_out, int out_size) {
    const float* x   = (const float*)d_in[0];
    const int*   ei  = (const int*)d_in[1];
    const float* W1  = (const float*)d_in[2];
    const float* b1  = (const float*)d_in[3];
    const float* W2  = (const float*)d_in[4];
    const float* b2  = (const float*)d_in[5];
    const float* g1  = (const float*)d_in[6];
    const float* be1 = (const float*)d_in[7];
    const float* g2  = (const float*)d_in[8];
    const float* be2 = (const float*)d_in[9];
    const float* pa  = (const float*)d_in[10];
    float* out = (float*)d_out;

    const int TB = 256;
    // CSR build (recomputed every launch; edges are an input)
    k_zero_deg<<<(N_NODES + TB - 1) / TB, TB>>>();
    k_count<<<(E_EDGES + TB - 1) / TB, TB>>>(ei);
    k_bsum<<<SCAN_NBLK, SCAN_BLK>>>();
    k_scanpart<<<1, 128>>>();
    k_apply<<<SCAN_NBLK, SCAN_BLK>>>();
    k_fill<<<(E_EDGES + TB - 1) / TB, TB>>>(ei);

    int gemm_blocks = (N_NODES + 127) / 128;
    int agg_blocks = (N_NODES + 7) / 8;  // 8 warps/block, warp per node

    // layer 1: gemm(x,W1) -> g_hs ; agg -> g_act
    k_gemm<CIN><<<gemm_blocks, 256>>>(x, W1);
    k_agg<<<agg_blocks, 256>>>(b1, g1, be1, pa, nullptr);
    // layer 2: gemm(g_act,W2) -> g_hs ; agg -> out
    k_gemm<HDIM><<<gemm_blocks, 256>>>(nullptr, W2);
    k_agg<<<agg_blocks, 256>>>(b2, g2, be2, pa, out);
}

// round 17
// speedup vs baseline: 1.2114x; 1.0462x over previous
#include <cuda_runtime.h>
#include <cstdint>

#define N_NODES 50000
#define E_EDGES 800000
#define HDIM    96
#define CIN     128

#define SCAN_BLK 512
#define SCAN_NBLK ((N_NODES + SCAN_BLK - 1) / SCAN_BLK)   // 98

// ---------------- device scratch (no allocations allowed) ----------------
__device__ int   g_edeg[N_NODES];        // zero-initialized; k_apply re-zeroes after read
__device__ int   g_rowstart[N_NODES + 1];
__device__ int   g_pos[N_NODES];
__device__ float g_dinv[N_NODES];
__device__ int   g_csr[E_EDGES];
__device__ int   g_part[SCAN_NBLK];      // per-block sums
__device__ float g_hs[(size_t)N_NODES * HDIM];   // X@W (unscaled)
__device__ float g_act[(size_t)N_NODES * HDIM];  // layer-1 activations

// ---------------- CSR build ----------------
__global__ void k_count(const int* __restrict__ ei) {
    int e = blockIdx.x * blockDim.x + threadIdx.x;
    if (e < E_EDGES) atomicAdd(&g_edeg[ei[E_EDGES + e]], 1);
}

// per-block sums of g_edeg
__global__ void __launch_bounds__(SCAN_BLK) k_bsum() {
    __shared__ int wsum[SCAN_BLK / 32];
    int i = blockIdx.x * SCAN_BLK + threadIdx.x;
    int lane = threadIdx.x & 31, wid = threadIdx.x >> 5;
    int v = (i < N_NODES) ? g_edeg[i] : 0;
    int s = v;
    #pragma unroll
    for (int off = 16; off; off >>= 1) s += __shfl_xor_sync(0xffffffffu, s, off);
    if (lane == 0) wsum[wid] = s;
    __syncthreads();
    if (wid == 0) {
        int t = (lane < SCAN_BLK / 32) ? wsum[lane] : 0;
        #pragma unroll
        for (int off = 16; off; off >>= 1) t += __shfl_xor_sync(0xffffffffu, t, off);
        if (lane == 0) g_part[blockIdx.x] = t;
    }
}

// local exclusive scan + decoupled lookback over g_part -> rowstart/pos/dinv.
// Also zeroes g_edeg for the next launch (self-restoring invariant).
__global__ void __launch_bounds__(SCAN_BLK) k_apply() {
    __shared__ int warp_off[SCAN_BLK / 32];
    __shared__ int s_boff;
    int tid = threadIdx.x, lane = tid & 31, wid = tid >> 5;
    int i = blockIdx.x * SCAN_BLK + tid;
    int v = 0;
    if (i < N_NODES) {
        v = g_edeg[i];
        g_edeg[i] = 0;                   // restore zero for next launch
    }
    // lookback: sum of g_part[0..bid-1]
    int acc = 0;
    for (int t = tid; t < blockIdx.x; t += SCAN_BLK) acc += g_part[t];
    #pragma unroll
    for (int off = 16; off; off >>= 1) acc += __shfl_xor_sync(0xffffffffu, acc, off);
    if (tid == 0) s_boff = 0;
    // local warp inclusive scan
    int incl = v;
    #pragma unroll
    for (int off = 1; off < 32; off <<= 1) {
        int u = __shfl_up_sync(0xffffffffu, incl, off);
        if (lane >= off) incl += u;
    }
    if (lane == 31) warp_off[wid] = incl;
    __syncthreads();
    if (lane == 0 && acc) atomicAdd(&s_boff, acc);
    if (wid == 0) {
        int ws = (lane < SCAN_BLK / 32) ? warp_off[lane] : 0;
        int wincl = ws;
        #pragma unroll
        for (int off = 1; off < 32; off <<= 1) {
            int u = __shfl_up_sync(0xffffffffu, wincl, off);
            if (lane >= off) wincl += u;
        }
        if (lane < SCAN_BLK / 32) warp_off[lane] = wincl - ws;
    }
    __syncthreads();
    if (i < N_NODES) {
        int excl = (incl - v) + warp_off[wid] + s_boff;
        g_rowstart[i] = excl;
        g_pos[i] = excl;
        g_dinv[i] = rsqrtf((float)(v + 1));   // deg includes self-loop
        if (i == N_NODES - 1) g_rowstart[N_NODES] = excl + v;
    }
}

__global__ void k_fill(const int* __restrict__ ei) {
    int e = blockIdx.x * blockDim.x + threadIdx.x;
    if (e < E_EDGES) {
        int dst = ei[E_EDGES + e];
        int src = ei[e];
        int slot = atomicAdd(&g_pos[dst], 1);
        g_csr[slot] = src;
    }
}

// ---------------- GEMM: g_hs = X @ W (unscaled), packed f32x2 ----------------
// X = X_ext if non-null, else g_act. Tile 128 rows x 96 cols, 256 threads.
// Each thread: 8 rows x 3 adjacent col-PAIRS, accumulated in fma.rn.f32x2.
// No dependency on the CSR/degree pipeline -> overlappable with it.
template <int KDIM>
__global__ void __launch_bounds__(256) k_gemm(const float* __restrict__ X_ext,
                                              const float* __restrict__ W) {
    const float* X = X_ext ? X_ext : (const float*)g_act;
    __shared__ unsigned long long Xs2[128 * 33];
    __shared__ float Ws[32 * 96];
    int tid = threadIdx.x;
    int txc = tid & 15;        // col-pair group: pairs at c = txc*2 + 32*j, j=0..2
    int tyr = tid >> 4;        // row group: rows = tyr*8 + i, i=0..7
    int rbase = blockIdx.x * 128;

    unsigned long long acc[8][3];
    #pragma unroll
    for (int i = 0; i < 8; i++)
        #pragma unroll
        for (int j = 0; j < 3; j++) acc[i][j] = 0ull;

    for (int k0 = 0; k0 < KDIM; k0 += 32) {
        __syncthreads();
        #pragma unroll
        for (int t = tid; t < 1024; t += 256) {
            int row = t >> 3;
            int kk4 = (t & 7) << 2;
            int gr = rbase + row;
            float4 v = make_float4(0.f, 0.f, 0.f, 0.f);
            if (gr < N_NODES)
                v = *reinterpret_cast<const float4*>(X + (size_t)gr * KDIM + k0 + kk4);
            int base = row * 33 + kk4;
            ((float2*)&Xs2[base + 0])[0] = make_float2(v.x, v.x);
            ((float2*)&Xs2[base + 1])[0] = make_float2(v.y, v.y);
            ((float2*)&Xs2[base + 2])[0] = make_float2(v.z, v.z);
            ((float2*)&Xs2[base + 3])[0] = make_float2(v.w, v.w);
        }
        #pragma unroll
        for (int t = tid; t < 768; t += 256) {
            int kk = t / 24;
            int cc = (t % 24) << 2;
            *reinterpret_cast<float4*>(&Ws[kk * 96 + cc]) =
                *reinterpret_cast<const float4*>(W + (size_t)(k0 + kk) * HDIM + cc);
        }
        __syncthreads();
        #pragma unroll 4
        for (int kk = 0; kk < 32; kk++) {
            unsigned long long xv[8], wv[3];
            #pragma unroll
            for (int i = 0; i < 8; i++)
                xv[i] = Xs2[(tyr * 8 + i) * 33 + kk];
            #pragma unroll
            for (int j = 0; j < 3; j++)
                wv[j] = *reinterpret_cast<const unsigned long long*>(
                            &Ws[kk * 96 + txc * 2 + 32 * j]);
            #pragma unroll
            for (int i = 0; i < 8; i++)
                #pragma unroll
                for (int j = 0; j < 3; j++)
                    asm("fma.rn.f32x2 %0, %1, %2, %0;"
                        : "+l"(acc[i][j]) : "l"(xv[i]), "l"(wv[j]));
        }
    }

    #pragma unroll
    for (int i = 0; i < 8; i++) {
        int gr = rbase + tyr * 8 + i;
        if (gr < N_NODES) {
            #pragma unroll
            for (int j = 0; j < 3; j++)
                *reinterpret_cast<float2*>(
                    g_hs + (size_t)gr * HDIM + txc * 2 + 32 * j) =
                    *reinterpret_cast<float2*>(&acc[i][j]);
        }
    }
}

// ---------------- aggregate + bias + layernorm + prelu, warp per node ----------------
// Reads g_hs (unscaled); per-edge FFMA with dinv[src]; final scale by dinv[dst].
__global__ void __launch_bounds__(256) k_agg(const float* __restrict__ bias,
                                             const float* __restrict__ gam,
                                             const float* __restrict__ bet,
                                             const float* __restrict__ pa,
                                             float* __restrict__ out_ext) {
    const float4* hs4 = (const float4*)g_hs;   // 24 float4 per row
    float* outp = out_ext ? out_ext : (float*)g_act;

    int warp = (blockIdx.x * blockDim.x + threadIdx.x) >> 5;
    int lane = threadIdx.x & 31;
    if (warp >= N_NODES) return;
    int node = warp;
    int start = g_rowstart[node];
    int end = g_rowstart[node + 1];
    bool act = lane < 24;

    float4 A = make_float4(0.f, 0.f, 0.f, 0.f);
    float4 C = make_float4(0.f, 0.f, 0.f, 0.f);
    for (int e0 = start; e0 < end; e0 += 32) {
        int cnt = min(32, end - e0);
        int s_idx = 0; float s_div = 0.f;
        if (lane < cnt) {
            s_idx = g_csr[e0 + lane];
            s_div = g_dinv[s_idx];
        }
        int j = 0;
        for (; j + 2 <= cnt; j += 2) {
            int sj0 = __shfl_sync(0xffffffffu, s_idx, j);
            int sj1 = __shfl_sync(0xffffffffu, s_idx, j + 1);
            float dj0 = __shfl_sync(0xffffffffu, s_div, j);
            float dj1 = __shfl_sync(0xffffffffu, s_div, j + 1);
            if (act) {
                float4 v0 = __ldg(&hs4[(size_t)sj0 * 24 + lane]);
                float4 v1 = __ldg(&hs4[(size_t)sj1 * 24 + lane]);
                A.x = fmaf(v0.x, dj0, A.x); A.y = fmaf(v0.y, dj0, A.y);
                A.z = fmaf(v0.z, dj0, A.z); A.w = fmaf(v0.w, dj0, A.w);
                C.x = fmaf(v1.x, dj1, C.x); C.y = fmaf(v1.y, dj1, C.y);
                C.z = fmaf(v1.z, dj1, C.z); C.w = fmaf(v1.w, dj1, C.w);
            }
        }
        if (j < cnt) {
            int sj = __shfl_sync(0xffffffffu, s_idx, j);
            float dj = __shfl_sync(0xffffffffu, s_div, j);
            if (act) {
                float4 v = __ldg(&hs4[(size_t)sj * 24 + lane]);
                A.x = fmaf(v.x, dj, A.x); A.y = fmaf(v.y, dj, A.y);
                A.z = fmaf(v.z, dj, A.z); A.w = fmaf(v.w, dj, A.w);
            }
        }
    }
    float dv = g_dinv[node];
    float4 bb = make_float4(0.f, 0.f, 0.f, 0.f);
    float4 gg = bb, ee = bb, aa = bb;
    if (act) {
        // self-loop: h[i]*dinv[i] (outer dv applied below -> dinv[i]^2 total)
        float4 vs = __ldg(&hs4[(size_t)node * 24 + lane]);
        A.x = fmaf(vs.x, dv, A.x + C.x); A.y = fmaf(vs.y, dv, A.y + C.y);
        A.z = fmaf(vs.z, dv, A.z + C.z); A.w = fmaf(vs.w, dv, A.w + C.w);
        bb = *(const float4*)(bias + lane * 4);
        gg = *(const float4*)(gam  + lane * 4);
        ee = *(const float4*)(bet  + lane * 4);
        aa = *(const float4*)(pa   + lane * 4);
    }

    float t0 = A.x * dv + bb.x;
    float t1 = A.y * dv + bb.y;
    float t2 = A.z * dv + bb.z;
    float t3 = A.w * dv + bb.w;
    if (!act) { t0 = t1 = t2 = t3 = 0.f; }

    // layernorm over 96 channels (4 per active lane)
    float s = t0 + t1 + t2 + t3;
    #pragma unroll
    for (int off = 16; off; off >>= 1) s += __shfl_xor_sync(0xffffffffu, s, off);
    float mu = s * (1.0f / 96.0f);
    float d0 = t0 - mu, d1 = t1 - mu, d2 = t2 - mu, d3 = t3 - mu;
    float q = act ? (d0 * d0 + d1 * d1 + d2 * d2 + d3 * d3) : 0.f;
    #pragma unroll
    for (int off = 16; off; off >>= 1) q += __shfl_xor_sync(0xffffffffu, q, off);
    float rstd = rsqrtf(q * (1.0f / 96.0f) + 1e-5f);

    if (act) {
        float y0 = d0 * rstd * gg.x + ee.x;
        float y1 = d1 * rstd * gg.y + ee.y;
        float y2 = d2 * rstd * gg.z + ee.z;
        float y3 = d3 * rstd * gg.w + ee.w;
        if (y0 < 0.f) y0 *= aa.x;
        if (y1 < 0.f) y1 *= aa.y;
        if (y2 < 0.f) y2 *= aa.z;
        if (y3 < 0.f) y3 *= aa.w;
        ((float4*)(outp + (size_t)node * HDIM))[lane] = make_float4(y0, y1, y2, y3);
    }
}

extern "C" void kernel_launch(void* const* d_in, const int* in_sizes, int n_in,
                              void* d_out, int out_size) {
    const float* x   = (const float*)d_in[0];
    const int*   ei  = (const int*)d_in[1];
    const float* W1  = (const float*)d_in[2];
    const float* b1  = (const float*)d_in[3];
    const float* W2  = (const float*)d_in[4];
    const float* b2  = (const float*)d_in[5];
    const float* g1  = (const float*)d_in[6];
    const float* be1 = (const float*)d_in[7];
    const float* g2  = (const float*)d_in[8];
    const float* be2 = (const float*)d_in[9];
    const float* pa  = (const float*)d_in[10];
    float* out = (float*)d_out;

    // side stream + fork/join events (created once during the uncaptured
    // correctness call; scheduling resources, not device allocations)
    static cudaStream_t sB = [] {
        cudaStream_t s; cudaStreamCreateWithFlags(&s, cudaStreamNonBlocking); return s;
    }();
    static cudaEvent_t evFork = [] {
        cudaEvent_t e; cudaEventCreateWithFlags(&e, cudaEventDisableTiming); return e;
    }();
    static cudaEvent_t evJoin = [] {
        cudaEvent_t e; cudaEventCreateWithFlags(&e, cudaEventDisableTiming); return e;
    }();

    const int TB = 256;
    int gemm_blocks = (N_NODES + 127) / 128;
    int agg_blocks = (N_NODES + 7) / 8;  // 8 warps/block, warp per node

    // fork: CSR pipeline on sB, GEMM1 on main stream (independent of edges)
    cudaEventRecord(evFork, 0);
    cudaStreamWaitEvent(sB, evFork, 0);
    k_count<<<(E_EDGES + TB - 1) / TB, TB, 0, sB>>>(ei);
    k_bsum<<<SCAN_NBLK, SCAN_BLK, 0, sB>>>();
    k_apply<<<SCAN_NBLK, SCAN_BLK, 0, sB>>>();
    k_fill<<<(E_EDGES + TB - 1) / TB, TB, 0, sB>>>(ei);
    cudaEventRecord(evJoin, sB);

    k_gemm<CIN><<<gemm_blocks, 256>>>(x, W1);     // overlaps CSR build

    // join, then the dependent tail
    cudaStreamWaitEvent(0, evJoin, 0);
    k_agg<<<agg_blocks, 256>>>(b1, g1, be1, pa, nullptr);
    k_gemm<HDIM><<<gemm_blocks, 256>>>(nullptr, W2);
    k_agg<<<agg_blocks, 256>>>(b2, g2, be2, pa, out);
}